// round 7
// baseline (speedup 1.0000x reference)
#include <cuda_runtime.h>

#define NB     64
#define NPER   2048
#define NTOT   131072          // NB*NPER
#define EE     1048576
#define KSEL   1639
#define PTOT   104896          // NB*KSEL
#define RANK_ASC 209715        // EE-1 - int(0.8*(EE-1))

// output layout (float32, concatenated in reference return order)
#define O1 6713344             // PTOT*64
#define O2 8810496             // O1 + 2*EE
#define O3 17199104            // O2 + EE*8
#define O4 17304000            // O3 + PTOT

__device__ int      g_perm[PTOT];
__device__ int      g_newidx[NTOT];
__device__ unsigned g_Su[EE];            // order-preserving uint key of S
__device__ unsigned g_h1[65536];
__device__ unsigned g_h2[65536];
__device__ unsigned g_psum[64];
__device__ unsigned g_binT;
__device__ unsigned g_rank2;
__device__ unsigned g_uth;

__device__ __forceinline__ unsigned f2u(float f) {
    unsigned u = __float_as_uint(f);
    return (u & 0x80000000u) ? ~u : (u | 0x80000000u);
}

// Zero hist1 + write batch_out (independent of topk: batch_out[p] = p/KSEL).
__global__ void k_zeroA(float* __restrict__ out) {
    int t = blockIdx.x * blockDim.x + threadIdx.x;
    if (t < 16384) ((uint4*)g_h1)[t] = make_uint4(0, 0, 0, 0);
    if (t < PTOT) out[O3 + t] = (float)(t / KSEL);
}

__global__ void k_zeroB() {
    int t = blockIdx.x * blockDim.x + threadIdx.x;
    ((uint4*)g_h2)[t] = make_uint4(0, 0, 0, 0);
}

// Per-graph bitonic sort of (score desc, idx asc); writes perm + new_idx.
__global__ void k_topk(const float* __restrict__ score) {
    __shared__ unsigned long long keys[NPER];
    int b = blockIdx.x, t = threadIdx.x;
    for (int i = t; i < NPER; i += blockDim.x) {
        unsigned su = f2u(score[b * NPER + i]);
        keys[i] = (((unsigned long long)(~su)) << 32) | (unsigned)i;
    }
    __syncthreads();
    for (int k = 2; k <= NPER; k <<= 1) {
        for (int j = k >> 1; j > 0; j >>= 1) {
            for (int i = t; i < NPER; i += blockDim.x) {
                int ixj = i ^ j;
                if (ixj > i) {
                    unsigned long long a = keys[i], c = keys[ixj];
                    bool up = ((i & k) == 0);
                    if ((a > c) == up) { keys[i] = c; keys[ixj] = a; }
                }
            }
            __syncthreads();
        }
    }
    for (int i = t; i < NPER; i += blockDim.x) {
        int local = (int)(keys[i] & 0xFFFFFFFFull);
        int node  = b * NPER + local;
        if (i < KSEL) {
            int p = b * KSEL + i;
            g_perm[p] = node;
            g_newidx[node] = p;
        } else {
            g_newidx[node] = -1;
        }
    }
}

// S kernel only: 4 edges per 16-lane group, 8 independent row-LDGs in flight.
// S[e]=exp(||x[row]-x[col]||), exact fp32. Short chain: ei(int4) -> rows ->
// interleaved shuffles -> Su store + hist atomic. No output tail.
__global__ void __launch_bounds__(256, 4) k_S(const int* __restrict__ ei,
                                              const float4* __restrict__ xv) {
    unsigned gid = blockIdx.x * blockDim.x + threadIdx.x;   // EE*4 threads
    int lane = threadIdx.x & 15;
    unsigned grp = gid >> 4;                                 // 0 .. EE/4-1
    int4 rr = __ldg(&((const int4*)ei)[grp]);
    int4 cc = __ldg(&((const int4*)ei)[EE / 4 + grp]);
    float4 a0 = __ldg(&xv[(size_t)rr.x * 16 + lane]);
    float4 b0 = __ldg(&xv[(size_t)cc.x * 16 + lane]);
    float4 a1 = __ldg(&xv[(size_t)rr.y * 16 + lane]);
    float4 b1 = __ldg(&xv[(size_t)cc.y * 16 + lane]);
    float4 a2 = __ldg(&xv[(size_t)rr.z * 16 + lane]);
    float4 b2 = __ldg(&xv[(size_t)cc.z * 16 + lane]);
    float4 a3 = __ldg(&xv[(size_t)rr.w * 16 + lane]);
    float4 b3 = __ldg(&xv[(size_t)cc.w * 16 + lane]);
    float dx, dy, dz, dw;
    dx = a0.x - b0.x; dy = a0.y - b0.y; dz = a0.z - b0.z; dw = a0.w - b0.w;
    float sq0 = dx * dx + dy * dy + dz * dz + dw * dw;
    dx = a1.x - b1.x; dy = a1.y - b1.y; dz = a1.z - b1.z; dw = a1.w - b1.w;
    float sq1 = dx * dx + dy * dy + dz * dz + dw * dw;
    dx = a2.x - b2.x; dy = a2.y - b2.y; dz = a2.z - b2.z; dw = a2.w - b2.w;
    float sq2 = dx * dx + dy * dy + dz * dz + dw * dw;
    dx = a3.x - b3.x; dy = a3.y - b3.y; dz = a3.z - b3.z; dw = a3.w - b3.w;
    float sq3 = dx * dx + dy * dy + dz * dz + dw * dw;
#pragma unroll
    for (int o = 8; o; o >>= 1) {    // 4 independent shuffle chains, interleaved
        sq0 += __shfl_xor_sync(0xFFFFFFFFu, sq0, o, 16);
        sq1 += __shfl_xor_sync(0xFFFFFFFFu, sq1, o, 16);
        sq2 += __shfl_xor_sync(0xFFFFFFFFu, sq2, o, 16);
        sq3 += __shfl_xor_sync(0xFFFFFFFFu, sq3, o, 16);
    }
    if (lane < 4) {
        float sq = (lane == 0) ? sq0 : (lane == 1) ? sq1 : (lane == 2) ? sq2 : sq3;
        float S = expf(sqrtf(sq));   // sq==0 -> S=1, matches _safe_norm forward
        unsigned u = f2u(S);
        g_Su[grp * 4 + lane] = u;
        atomicAdd(&g_h1[u >> 16], 1u);
    }
}

// Parallel partial sums: 64 blocks x 256 threads, each thread 4 bins (uint4).
__global__ void k_sum(int pass) {
    const uint4* hist4 = (const uint4*)(pass ? g_h2 : g_h1);
    __shared__ unsigned sh[8];
    int t = threadIdx.x;
    uint4 v = hist4[blockIdx.x * 256 + t];
    unsigned s = v.x + v.y + v.z + v.w;
#pragma unroll
    for (int o = 16; o; o >>= 1) s += __shfl_xor_sync(0xFFFFFFFFu, s, o);
    if ((t & 31) == 0) sh[t >> 5] = s;
    __syncthreads();
    if (t < 8) {
        s = sh[t];
#pragma unroll
        for (int o = 4; o; o >>= 1) s += __shfl_xor_sync(0xFFu, s, o, 8);
        if (t == 0) g_psum[blockIdx.x] = s;
    }
}

// One block: psums staged via SMEM, then 1024 threads shuffle-scan the
// winning 1024-bin chunk.
__global__ void k_find(int pass) {
    __shared__ unsigned warpsum[32];
    __shared__ unsigned spsum[64];
    __shared__ unsigned s_excl;
    __shared__ int s_blk;
    const unsigned* hist = pass ? g_h2 : g_h1;
    int t = threadIdx.x;
    unsigned target = pass ? g_rank2 : (unsigned)RANK_ASC;
    if (t < 64) spsum[t] = g_psum[t];
    __syncthreads();
    if (t == 0) {
        unsigned cum = 0;
        int B = 0;
        for (int i = 0; i < 64; i++) {
            unsigned p = spsum[i];
            if (target < cum + p) { B = i; break; }
            cum += p;
        }
        s_excl = cum; s_blk = B;
    }
    __syncthreads();
    int B = s_blk;
    unsigned h = hist[B * 1024 + t];
    unsigned inc = h;
#pragma unroll
    for (int o = 1; o < 32; o <<= 1) {
        unsigned n = __shfl_up_sync(0xFFFFFFFFu, inc, o);
        if ((t & 31) >= o) inc += n;
    }
    if ((t & 31) == 31) warpsum[t >> 5] = inc;
    __syncthreads();
    if (t < 32) {
        unsigned w = warpsum[t];
#pragma unroll
        for (int o = 1; o < 32; o <<= 1) {
            unsigned n = __shfl_up_sync(0xFFFFFFFFu, w, o);
            if (t >= o) w += n;
        }
        warpsum[t] = w;
    }
    __syncthreads();
    unsigned incl = inc + ((t >= 32) ? warpsum[(t >> 5) - 1] : 0u);
    unsigned excl = s_excl + incl - h;
    if (target >= excl && target < excl + h) {
        unsigned bin = (unsigned)(B * 1024 + t);
        if (pass == 0) { g_binT = bin; g_rank2 = target - excl; }
        else           { g_uth = (g_binT << 16) | bin; }
    }
}

__global__ void k_hist2() {
    int e = blockIdx.x * blockDim.x + threadIdx.x;
    unsigned u = g_Su[e];
    if ((u >> 16) == g_binT) atomicAdd(&g_h2[u & 0xFFFFu], 1u);
}

// Streaming edge outputs (after pass 2, so select is fused here too):
// 2 threads per edge: remapped indices, masked attrs, select flag.
__global__ void k_edges(const int* __restrict__ ei, const float4* __restrict__ attr4,
                        float* __restrict__ out) {
    int h = blockIdx.x * blockDim.x + threadIdx.x;   // EE*2 threads
    int e = h >> 1, half = h & 1;
    int r = ei[e], c = ei[EE + e];
    int nr = g_newidx[r], nc = g_newidx[c];
    bool valid = (nr >= 0) && (nc >= 0);
    if (half == 0) {
        out[O1 + e] = valid ? (float)nr : -1.0f;
    } else {
        out[O1 + EE + e] = valid ? (float)nc : -1.0f;
        out[O4 + e] = (g_Su[e] > g_uth) ? 1.0f : 0.0f;
    }
    float4 av = valid ? attr4[e * 2 + half] : make_float4(0, 0, 0, 0);
    ((float4*)(out + O2))[e * 2 + half] = av;
}

// x_out gather: 16 threads (float4 each) per selected row (exact fp32).
__global__ void k_final(const float4* __restrict__ xv, float* __restrict__ out) {
    int t = blockIdx.x * blockDim.x + threadIdx.x;
    if (t < PTOT * 16) {
        int p = t >> 4, j = t & 15;
        int node = g_perm[p];
        ((float4*)out)[p * 16 + j] = xv[(size_t)node * 16 + j];
    }
}

extern "C" void kernel_launch(void* const* d_in, const int* in_sizes, int n_in,
                              void* d_out, int out_size) {
    const float* x    = (const float*)d_in[0];
    const float* xs   = (const float*)d_in[1];
    const int*   ei   = (const int*)d_in[2];
    const float* attr = (const float*)d_in[3];
    float* out = (float*)d_out;

    k_zeroA<<<(PTOT + 255) / 256, 256>>>(out);     // #1
    k_zeroB<<<64, 256>>>();                        // #2
    k_topk<<<NB, 1024>>>(xs);                      // #3
    k_S<<<EE * 4 / 256, 256>>>(ei, (const float4*)x);   // #4 (ncu capture slot)
    k_sum<<<64, 256>>>(0);                         // #5
    k_find<<<1, 1024>>>(0);                        // #6
    k_hist2<<<EE / 256, 256>>>();                  // #7
    k_sum<<<64, 256>>>(1);                         // #8
    k_find<<<1, 1024>>>(1);                        // #9
    k_edges<<<EE * 2 / 256, 256>>>(ei, (const float4*)attr, out);  // #10
    k_final<<<PTOT * 16 / 256, 256>>>((const float4*)x, out);      // #11
}